// round 5
// baseline (speedup 1.0000x reference)
#include <cuda_runtime.h>
#include <math.h>
#include <stdint.h>

#define B_ 4
#define S_ 2048
#define D_ 2048
#define H_ 16
#define HD_ 128
#define E_ 6144     // 3*D
#define BS_ 8192    // B*S
#define EPS_ 1.1920929e-07f

// Scratch (allocation-free rule: __device__ globals)
__device__ float g_qkv[(size_t)BS_ * E_];   // [8192, 6144] (tf32-rounded values)
__device__ float g_att[(size_t)BS_ * D_];   // [8192, 2048] (tf32-rounded)
__device__ float g_xr [(size_t)BS_ * D_];   // rounded x
__device__ float g_wir[(size_t)E_  * D_];   // rounded w_in
__device__ float g_wor[(size_t)D_  * D_];   // rounded w_out

__device__ __forceinline__ unsigned tf32_of(float x) {
    unsigned r;
    asm("cvt.rna.tf32.f32 %0, %1;" : "=r"(r) : "f"(x));
    return r;
}
__device__ __forceinline__ float tf32f(float x) { return __uint_as_float(tf32_of(x)); }

__device__ __forceinline__ float ex2f(float x) {
    float r;
    asm("ex2.approx.f32 %0, %1;" : "=f"(r) : "f"(x));
    return r;
}

__device__ __forceinline__ void mma_tf32(float& c0, float& c1, float& c2, float& c3,
                                         unsigned a0, unsigned a1, unsigned a2, unsigned a3,
                                         unsigned b0, unsigned b1) {
    asm volatile(
        "mma.sync.aligned.m16n8k8.row.col.f32.tf32.tf32.f32 "
        "{%0,%1,%2,%3}, {%4,%5,%6,%7}, {%8,%9}, {%0,%1,%2,%3};\n"
        : "+f"(c0), "+f"(c1), "+f"(c2), "+f"(c3)
        : "r"(a0), "r"(a1), "r"(a2), "r"(a3), "r"(b0), "r"(b1));
}

__device__ __forceinline__ void cp_async16(void* sdst, const void* gsrc) {
    unsigned s = (unsigned)__cvta_generic_to_shared(sdst);
    asm volatile("cp.async.cg.shared.global [%0], [%1], 16;\n" :: "r"(s), "l"(gsrc));
}
__device__ __forceinline__ void cp_commit() { asm volatile("cp.async.commit_group;\n"); }
__device__ __forceinline__ void cp_wait0() { asm volatile("cp.async.wait_group 0;\n"); }
__device__ __forceinline__ void cp_wait1() { asm volatile("cp.async.wait_group 1;\n"); }

// ---------------------------------------------------------------------------
// Prepass: tf32-round an array (rna) so cp.async-fed MMAs see rounded operands.
// ---------------------------------------------------------------------------
__global__ void round_tf32(const float* __restrict__ src, float* __restrict__ dst, int n4)
{
    int i = blockIdx.x * blockDim.x + threadIdx.x;
    int stride = gridDim.x * blockDim.x;
    for (; i < n4; i += stride) {
        float4 v = reinterpret_cast<const float4*>(src)[i];
        v.x = tf32f(v.x); v.y = tf32f(v.y); v.z = tf32f(v.z); v.w = tf32f(v.w);
        reinterpret_cast<float4*>(dst)[i] = v;
    }
}

// ---------------------------------------------------------------------------
// TF32 GEMM v2: C[m][n] = sum_k A[m][k]*W[n][k]. CTA 128x128, BK=16, 128 thr,
// 4 warps 2x2, warp tile 64x64. 3-stage cp.async ring, one sync per k-chunk.
// smem stride 20 (==4 mod 32 -> conflict-free frag loads).
// ---------------------------------------------------------------------------
#define GLD 20
#define GST (128 * GLD)

template<bool ROUND>
__global__ __launch_bounds__(128, 2) void gemm_tf32_v2(
    const float* __restrict__ A, const float* __restrict__ W,
    float* __restrict__ C, int M, int N, int K)
{
    extern __shared__ float smem[];
    float* sA = smem;             // [3][GST]
    float* sB = smem + 3 * GST;   // [3][GST]

    const int t    = threadIdx.x;
    const int warp = t >> 5;
    const int lane = t & 31;
    const int g    = lane >> 2;
    const int tq   = lane & 3;
    const int wy   = warp >> 1;    // 0..1
    const int wx   = warp & 1;     // 0..1
    const int m0   = blockIdx.y * 128;
    const int n0   = blockIdx.x * 128;

    const int lrow = t >> 2;       // 0..31
    const int lkq  = t & 3;

    const float* Ab = A + (size_t)m0 * K;
    const float* Wb = W + (size_t)n0 * K;

    float acc[4][8][4];
#pragma unroll
    for (int i = 0; i < 4; i++)
#pragma unroll
        for (int j = 0; j < 8; j++)
#pragma unroll
            for (int r = 0; r < 4; r++) acc[i][j][r] = 0.f;

    auto issue = [&](int kc, int st) {
        int k0 = kc * 16;
#pragma unroll
        for (int u = 0; u < 4; u++) {
            int row = lrow + u * 32;
            cp_async16(&sA[st * GST + row * GLD + lkq * 4],
                       Ab + (size_t)row * K + k0 + lkq * 4);
        }
#pragma unroll
        for (int u = 0; u < 4; u++) {
            int row = lrow + u * 32;
            cp_async16(&sB[st * GST + row * GLD + lkq * 4],
                       Wb + (size_t)row * K + k0 + lkq * 4);
        }
        cp_commit();
    };

    const int nk = K / 16;
    issue(0, 0);
    issue(1, 1);

    for (int kc = 0; kc < nk; kc++) {
        if (kc + 1 < nk) cp_wait1(); else cp_wait0();
        __syncthreads();
        if (kc + 2 < nk) issue(kc + 2, (kc + 2) % 3);
        const float* cA = &sA[(kc % 3) * GST];
        const float* cB = &sB[(kc % 3) * GST];
#pragma unroll
        for (int ks = 0; ks < 2; ks++) {
            unsigned af[4][4];
#pragma unroll
            for (int mt = 0; mt < 4; mt++) {
                const float* base = &cA[(wy * 64 + mt * 16 + g) * GLD + ks * 8 + tq];
                af[mt][0] = __float_as_uint(base[0]);
                af[mt][1] = __float_as_uint(base[8 * GLD]);
                af[mt][2] = __float_as_uint(base[4]);
                af[mt][3] = __float_as_uint(base[8 * GLD + 4]);
            }
            unsigned bf[8][2];
#pragma unroll
            for (int nt = 0; nt < 8; nt++) {
                const float* base = &cB[(wx * 64 + nt * 8 + g) * GLD + ks * 8 + tq];
                bf[nt][0] = __float_as_uint(base[0]);
                bf[nt][1] = __float_as_uint(base[4]);
            }
#pragma unroll
            for (int mt = 0; mt < 4; mt++)
#pragma unroll
                for (int nt = 0; nt < 8; nt++)
                    mma_tf32(acc[mt][nt][0], acc[mt][nt][1], acc[mt][nt][2], acc[mt][nt][3],
                             af[mt][0], af[mt][1], af[mt][2], af[mt][3],
                             bf[nt][0], bf[nt][1]);
        }
    }

#pragma unroll
    for (int mt = 0; mt < 4; mt++) {
        int r0 = m0 + wy * 64 + mt * 16 + g;
#pragma unroll
        for (int nt = 0; nt < 8; nt++) {
            int col = n0 + wx * 64 + nt * 8 + tq * 2;
            float c0 = acc[mt][nt][0], c1 = acc[mt][nt][1];
            float c2 = acc[mt][nt][2], c3 = acc[mt][nt][3];
            if (ROUND) { c0 = tf32f(c0); c1 = tf32f(c1); c2 = tf32f(c2); c3 = tf32f(c3); }
            *reinterpret_cast<float2*>(C + (size_t)r0 * N + col)       = make_float2(c0, c1);
            *reinterpret_cast<float2*>(C + (size_t)(r0 + 8) * N + col) = make_float2(c2, c3);
        }
    }
}

// ---------------------------------------------------------------------------
// RMSNorm over head_dim for Q and K parts of qkv, in place; tf32-rounds output.
// ---------------------------------------------------------------------------
__global__ void rmsnorm_qk(float* __restrict__ qkv,
                           const float* __restrict__ qg, const float* __restrict__ kg)
{
    int warp = (blockIdx.x * blockDim.x + threadIdx.x) >> 5;
    int lane = threadIdx.x & 31;
    const int half = B_ * S_ * H_;
    int part = warp / half;
    int rem  = warp % half;
    int bs   = rem / H_;
    int h    = rem % H_;
    float* p = qkv + (size_t)bs * E_ + part * D_ + h * HD_;

    float4 v = *reinterpret_cast<const float4*>(p + lane * 4);
    float ss = v.x*v.x + v.y*v.y + v.z*v.z + v.w*v.w;
#pragma unroll
    for (int o = 16; o; o >>= 1) ss += __shfl_xor_sync(0xffffffffu, ss, o);
    float scale = rsqrtf(ss * (1.0f / 128.0f) + EPS_);
    const float* gam = part ? kg : qg;
    float4 gv = *reinterpret_cast<const float4*>(gam + lane * 4);
    v.x = tf32f(v.x * scale * gv.x); v.y = tf32f(v.y * scale * gv.y);
    v.z = tf32f(v.z * scale * gv.z); v.w = tf32f(v.w * scale * gv.w);
    *reinterpret_cast<float4*>(p + lane * 4) = v;
}

// ---------------------------------------------------------------------------
// Causal flash attention v3: tf32 MMA, Q frags in registers, 3-stage cp.async
// K/V ring (one __syncthreads per kv-block), shuffle-based P C->A conversion,
// work-descending CTA order. 128 threads = 4 warps, BQ=64, BKV=32.
// ---------------------------------------------------------------------------
#define AKL 132                 // K row stride (mod 32 == 4)
#define AVL 136                 // V row stride (mod 32 == 8)
#define KST (32 * AKL)          // 4224 floats per K stage
#define VST (32 * AVL)          // 4352 floats per V stage

__global__ __launch_bounds__(128, 2) void attn_v3(
    const float* __restrict__ qkv, float* __restrict__ out)
{
    extern __shared__ float sm[];
    float* sK = sm;             // [3][KST]
    float* sV = sm + 3 * KST;   // [3][VST]

    const int t    = threadIdx.x;
    const int w    = t >> 5;
    const int lane = t & 31;
    const int g    = lane >> 2;
    const int tq   = lane & 3;

    const int bh   = blockIdx.x >> 5;
    const int qblk = 31 - (blockIdx.x & 31);   // longest work first
    const int b    = bh >> 4;
    const int h    = bh & 15;

    const float* qb = qkv + (size_t)b * S_ * E_ + h * HD_;
    const float* kb = qb + D_;
    const float* vb = qb + 2 * D_;
    const int q0  = qblk * 64;
    const int qg0 = q0 + w * 16 + g;
    const int qg1 = qg0 + 8;

    // Q fragments in registers (values pre-rounded by rmsnorm)
    unsigned qf[16][4];
#pragma unroll
    for (int ks = 0; ks < 16; ks++) {
        qf[ks][0] = __float_as_uint(qb[(size_t)qg0 * E_ + ks * 8 + tq]);
        qf[ks][1] = __float_as_uint(qb[(size_t)qg1 * E_ + ks * 8 + tq]);
        qf[ks][2] = __float_as_uint(qb[(size_t)qg0 * E_ + ks * 8 + tq + 4]);
        qf[ks][3] = __float_as_uint(qb[(size_t)qg1 * E_ + ks * 8 + tq + 4]);
    }

    float acc[16][4];
#pragma unroll
    for (int i = 0; i < 16; i++)
#pragma unroll
        for (int r = 0; r < 4; r++) acc[i][r] = 0.f;
    float m0r = -INFINITY, m1r = -INFINITY, l0 = 0.f, l1 = 0.f;
    const float sc2 = 0.08838834764831845f * 1.4426950408889634f;  // 1/sqrt(128)*log2(e)

    auto issue = [&](int j, int st) {
        int k0 = j * 32;
#pragma unroll
        for (int u = 0; u < 8; u++) {
            int i = u * 128 + t;
            int r = i >> 5, c4 = i & 31;
            cp_async16(&sK[st * KST + r * AKL + c4 * 4], kb + (size_t)(k0 + r) * E_ + c4 * 4);
            cp_async16(&sV[st * VST + r * AVL + c4 * 4], vb + (size_t)(k0 + r) * E_ + c4 * 4);
        }
        cp_commit();
    };

    const int nblk = 2 * qblk + 2;
    issue(0, 0);
    issue(1, 1);

    const int src0 = (lane & ~3) | (tq >> 1);
    const int src1 = src0 + 2;
    const bool odd = (tq & 1);

    for (int j = 0; j < nblk; j++) {
        if (j + 1 < nblk) cp_wait1(); else cp_wait0();
        __syncthreads();
        if (j + 2 < nblk) issue(j + 2, (j + 2) % 3);

        const float* cK = &sK[(j % 3) * KST];
        const float* cV = &sV[(j % 3) * VST];
        const int k0 = j * 32;

        // ---- S = Q K^T (m16 x n32, k=128) ----
        float sa[4][4];
#pragma unroll
        for (int nt = 0; nt < 4; nt++)
#pragma unroll
            for (int r = 0; r < 4; r++) sa[nt][r] = 0.f;
#pragma unroll
        for (int ks = 0; ks < 16; ks++) {
#pragma unroll
            for (int nt = 0; nt < 4; nt++) {
                const float* bbase = &cK[(nt * 8 + g) * AKL + ks * 8 + tq];
                unsigned b0 = __float_as_uint(bbase[0]);
                unsigned b1 = __float_as_uint(bbase[4]);
                mma_tf32(sa[nt][0], sa[nt][1], sa[nt][2], sa[nt][3],
                         qf[ks][0], qf[ks][1], qf[ks][2], qf[ks][3], b0, b1);
            }
        }

        // ---- scale (+mask) to log2 domain ----
        if (k0 + 31 > q0 + w * 16) {
#pragma unroll
            for (int nt = 0; nt < 4; nt++) {
                int kva = k0 + nt * 8 + tq * 2;
                sa[nt][0] = (kva     <= qg0) ? sa[nt][0] * sc2 : -INFINITY;
                sa[nt][1] = (kva + 1 <= qg0) ? sa[nt][1] * sc2 : -INFINITY;
                sa[nt][2] = (kva     <= qg1) ? sa[nt][2] * sc2 : -INFINITY;
                sa[nt][3] = (kva + 1 <= qg1) ? sa[nt][3] * sc2 : -INFINITY;
            }
        } else {
#pragma unroll
            for (int nt = 0; nt < 4; nt++)
#pragma unroll
                for (int r = 0; r < 4; r++) sa[nt][r] *= sc2;
        }

        float mx0 = -INFINITY, mx1 = -INFINITY;
#pragma unroll
        for (int nt = 0; nt < 4; nt++) {
            mx0 = fmaxf(mx0, fmaxf(sa[nt][0], sa[nt][1]));
            mx1 = fmaxf(mx1, fmaxf(sa[nt][2], sa[nt][3]));
        }
        mx0 = fmaxf(mx0, __shfl_xor_sync(0xffffffffu, mx0, 1));
        mx0 = fmaxf(mx0, __shfl_xor_sync(0xffffffffu, mx0, 2));
        mx1 = fmaxf(mx1, __shfl_xor_sync(0xffffffffu, mx1, 1));
        mx1 = fmaxf(mx1, __shfl_xor_sync(0xffffffffu, mx1, 2));

        float mn0 = fmaxf(m0r, mx0), mn1 = fmaxf(m1r, mx1);
        float al0 = ex2f(m0r - mn0), al1 = ex2f(m1r - mn1);
        float ll0 = 0.f, ll1 = 0.f;
#pragma unroll
        for (int nt = 0; nt < 4; nt++) {
            sa[nt][0] = ex2f(sa[nt][0] - mn0);
            sa[nt][1] = ex2f(sa[nt][1] - mn0);
            sa[nt][2] = ex2f(sa[nt][2] - mn1);
            sa[nt][3] = ex2f(sa[nt][3] - mn1);
            ll0 += sa[nt][0] + sa[nt][1];
            ll1 += sa[nt][2] + sa[nt][3];
            sa[nt][0] = tf32f(sa[nt][0]); sa[nt][1] = tf32f(sa[nt][1]);
            sa[nt][2] = tf32f(sa[nt][2]); sa[nt][3] = tf32f(sa[nt][3]);
        }
        ll0 += __shfl_xor_sync(0xffffffffu, ll0, 1);
        ll0 += __shfl_xor_sync(0xffffffffu, ll0, 2);
        ll1 += __shfl_xor_sync(0xffffffffu, ll1, 1);
        ll1 += __shfl_xor_sync(0xffffffffu, ll1, 2);
        l0 = l0 * al0 + ll0; l1 = l1 * al1 + ll1;
        m0r = mn0; m1r = mn1;

#pragma unroll
        for (int i = 0; i < 16; i++) {
            acc[i][0] *= al0; acc[i][1] *= al0;
            acc[i][2] *= al1; acc[i][3] *= al1;
        }

        // ---- PV: A-frags from C-frags via quad shuffles ----
#pragma unroll
        for (int ks = 0; ks < 4; ks++) {
            float e0 = __shfl_sync(0xffffffffu, sa[ks][0], src0);
            float e1 = __shfl_sync(0xffffffffu, sa[ks][1], src0);
            float f0 = __shfl_sync(0xffffffffu, sa[ks][0], src1);
            float f1 = __shfl_sync(0xffffffffu, sa[ks][1], src1);
            float e2 = __shfl_sync(0xffffffffu, sa[ks][2], src0);
            float e3 = __shfl_sync(0xffffffffu, sa[ks][3], src0);
            float f2 = __shfl_sync(0xffffffffu, sa[ks][2], src1);
            float f3 = __shfl_sync(0xffffffffu, sa[ks][3], src1);
            unsigned a0 = __float_as_uint(odd ? e1 : e0);
            unsigned a2 = __float_as_uint(odd ? f1 : f0);
            unsigned a1 = __float_as_uint(odd ? e3 : e2);
            unsigned a3 = __float_as_uint(odd ? f3 : f2);
            const float* vr0 = &cV[(ks * 8 + tq) * AVL];
            const float* vr1 = &cV[(ks * 8 + tq + 4) * AVL];
#pragma unroll
            for (int nt = 0; nt < 16; nt++) {
                unsigned b0 = __float_as_uint(vr0[nt * 8 + g]);
                unsigned b1 = __float_as_uint(vr1[nt * 8 + g]);
                mma_tf32(acc[nt][0], acc[nt][1], acc[nt][2], acc[nt][3],
                         a0, a1, a2, a3, b0, b1);
            }
        }
    }

    float inv0 = 1.0f / l0, inv1 = 1.0f / l1;
    float* o0 = out + (size_t)(b * S_ + qg0) * D_ + h * HD_;
    float* o1 = out + (size_t)(b * S_ + qg1) * D_ + h * HD_;
#pragma unroll
    for (int nt = 0; nt < 16; nt++) {
        int d = nt * 8 + tq * 2;
        *reinterpret_cast<float2*>(o0 + d) =
            make_float2(tf32f(acc[nt][0] * inv0), tf32f(acc[nt][1] * inv0));
        *reinterpret_cast<float2*>(o1 + d) =
            make_float2(tf32f(acc[nt][2] * inv1), tf32f(acc[nt][3] * inv1));
    }
}

// ---------------------------------------------------------------------------
extern "C" void kernel_launch(void* const* d_in, const int* in_sizes, int n_in,
                              void* d_out, int out_size)
{
    const float* x     = (const float*)d_in[0];
    const float* w_in  = (const float*)d_in[1];
    const float* w_out = (const float*)d_in[2];
    const float* qg    = (const float*)d_in[3];
    const float* kg    = (const float*)d_in[4];
    float* out = (float*)d_out;

    float *qkv, *att, *xr, *wir, *wor;
    cudaGetSymbolAddress((void**)&qkv, g_qkv);
    cudaGetSymbolAddress((void**)&att, g_att);
    cudaGetSymbolAddress((void**)&xr,  g_xr);
    cudaGetSymbolAddress((void**)&wir, g_wir);
    cudaGetSymbolAddress((void**)&wor, g_wor);

    // 0) tf32-round GEMM operands (rna; avoids biased truncation via cp.async)
    round_tf32<<<1184, 256>>>(x,     xr,  BS_ * D_ / 4);
    round_tf32<<<1184, 256>>>(w_in,  wir, E_  * D_ / 4);
    round_tf32<<<1184, 256>>>(w_out, wor, D_  * D_ / 4);

    const int gsm = 6 * GST * 4;                // 61440 B
    cudaFuncSetAttribute(gemm_tf32_v2<true>,  cudaFuncAttributeMaxDynamicSharedMemorySize, gsm);
    cudaFuncSetAttribute(gemm_tf32_v2<false>, cudaFuncAttributeMaxDynamicSharedMemorySize, gsm);

    // 1) QKV projection (rounded epilogue)
    gemm_tf32_v2<true><<<dim3(E_ / 128, BS_ / 128), 128, gsm>>>(xr, wir, qkv, BS_, E_, D_);

    // 2) RMSNorm q/k heads (rounded output)
    rmsnorm_qk<<<32768, 256>>>(qkv, qg, kg);

    // 3) causal attention (rounded output)
    const int asm_ = 3 * (KST + VST) * 4;       // 102912 B
    cudaFuncSetAttribute(attn_v3, cudaFuncAttributeMaxDynamicSharedMemorySize, asm_);
    attn_v3<<<64 * 32, 128, asm_>>>(qkv, att);

    // 4) output projection (full fp32 epilogue)
    gemm_tf32_v2<false><<<dim3(D_ / 128, BS_ / 128), 128, gsm>>>(att, wor, out, BS_, D_, D_);
}

// round 7
// speedup vs baseline: 1.0048x; 1.0048x over previous
#include <cuda_runtime.h>
#include <math.h>
#include <stdint.h>

#define B_ 4
#define S_ 2048
#define D_ 2048
#define H_ 16
#define HD_ 128
#define E_ 6144
#define BS_ 8192
#define EPS_ 1.1920929e-07f

__device__ float g_qkv[(size_t)BS_ * E_];
__device__ float g_att[(size_t)BS_ * D_];
__device__ float g_xr [(size_t)BS_ * D_];
__device__ float g_wir[(size_t)E_  * D_];
__device__ float g_wor[(size_t)D_  * D_];
__device__ float g_m2[1];

__device__ __forceinline__ unsigned tf32_of(float x) {
    unsigned r; asm("cvt.rna.tf32.f32 %0, %1;" : "=r"(r) : "f"(x)); return r;
}
__device__ __forceinline__ float tf32f(float x) { return __uint_as_float(tf32_of(x)); }
__device__ __forceinline__ float ex2f(float x) {
    float r; asm("ex2.approx.f32 %0, %1;" : "=f"(r) : "f"(x)); return r;
}
__device__ __forceinline__ void mma_tf32(float& c0, float& c1, float& c2, float& c3,
                                         unsigned a0, unsigned a1, unsigned a2, unsigned a3,
                                         unsigned b0, unsigned b1) {
    asm volatile("mma.sync.aligned.m16n8k8.row.col.f32.tf32.tf32.f32 "
        "{%0,%1,%2,%3}, {%4,%5,%6,%7}, {%8,%9}, {%0,%1,%2,%3};\n"
        : "+f"(c0), "+f"(c1), "+f"(c2), "+f"(c3)
        : "r"(a0), "r"(a1), "r"(a2), "r"(a3), "r"(b0), "r"(b1));
}
__device__ __forceinline__ void cp_async16(void* sdst, const void* gsrc) {
    unsigned s = (unsigned)__cvta_generic_to_shared(sdst);
    asm volatile("cp.async.cg.shared.global [%0], [%1], 16;\n" :: "r"(s), "l"(gsrc));
}
__device__ __forceinline__ void cp_commit() { asm volatile("cp.async.commit_group;\n"); }
__device__ __forceinline__ void cp_wait0() { asm volatile("cp.async.wait_group 0;\n"); }
__device__ __forceinline__ void cp_wait1() { asm volatile("cp.async.wait_group 1;\n"); }

// ---------------------------------------------------------------------------
__global__ void round_tf32(const float* __restrict__ src, float* __restrict__ dst, int n4)
{
    int i = blockIdx.x * blockDim.x + threadIdx.x;
    int st = gridDim.x * blockDim.x;
    for (; i < n4; i += st) {
        float4 v = reinterpret_cast<const float4*>(src)[i];
        v.x = tf32f(v.x); v.y = tf32f(v.y); v.z = tf32f(v.z); v.w = tf32f(v.w);
        reinterpret_cast<float4*>(dst)[i] = v;
    }
}

// softmax fixed-max bound (log2 domain): sqrt(128)*log2e * maxg_q * maxg_k, padded
__global__ void gmax_kernel(const float* __restrict__ qg, const float* __restrict__ kg,
                            float* __restrict__ o)
{
    int t = threadIdx.x;
    float mq = 0.f, mk = 0.f;
#pragma unroll
    for (int i = 0; i < 4; i++) {
        mq = fmaxf(mq, fabsf(qg[t + i * 32]));
        mk = fmaxf(mk, fabsf(kg[t + i * 32]));
    }
#pragma unroll
    for (int s = 16; s; s >>= 1) {
        mq = fmaxf(mq, __shfl_xor_sync(0xffffffffu, mq, s));
        mk = fmaxf(mk, __shfl_xor_sync(0xffffffffu, mk, s));
    }
    if (t == 0) o[0] = 16.32253f * mq * mk * 1.002f + 0.01f;
}

// ---------------------------------------------------------------------------
// TF32 GEMM (identical to R4 known-good)
// ---------------------------------------------------------------------------
#define GLD 20
#define GST (128 * GLD)
template<bool ROUND>
__global__ __launch_bounds__(128, 2) void gemm_tf32_v2(
    const float* __restrict__ A, const float* __restrict__ W,
    float* __restrict__ C, int M, int N, int K)
{
    extern __shared__ float smem[];
    float* sA = smem;
    float* sB = smem + 3 * GST;
    const int t = threadIdx.x, warp = t >> 5, lane = t & 31;
    const int g = lane >> 2, tq = lane & 3, wy = warp >> 1, wx = warp & 1;
    const int m0 = blockIdx.y * 128, n0 = blockIdx.x * 128;
    const int lrow = t >> 2, lkq = t & 3;
    const float* Ab = A + (size_t)m0 * K;
    const float* Wb = W + (size_t)n0 * K;
    float acc[4][8][4];
#pragma unroll
    for (int i = 0; i < 4; i++)
#pragma unroll
        for (int j = 0; j < 8; j++)
#pragma unroll
            for (int r = 0; r < 4; r++) acc[i][j][r] = 0.f;
    auto issue = [&](int kc, int st) {
        int k0 = kc * 16;
#pragma unroll
        for (int u = 0; u < 4; u++) {
            int row = lrow + u * 32;
            cp_async16(&sA[st * GST + row * GLD + lkq * 4], Ab + (size_t)row * K + k0 + lkq * 4);
        }
#pragma unroll
        for (int u = 0; u < 4; u++) {
            int row = lrow + u * 32;
            cp_async16(&sB[st * GST + row * GLD + lkq * 4], Wb + (size_t)row * K + k0 + lkq * 4);
        }
        cp_commit();
    };
    const int nk = K / 16;
    issue(0, 0); issue(1, 1);
    for (int kc = 0; kc < nk; kc++) {
        if (kc + 1 < nk) cp_wait1(); else cp_wait0();
        __syncthreads();
        if (kc + 2 < nk) issue(kc + 2, (kc + 2) % 3);
        const float* cA = &sA[(kc % 3) * GST];
        const float* cB = &sB[(kc % 3) * GST];
#pragma unroll
        for (int ks = 0; ks < 2; ks++) {
            unsigned af[4][4];
#pragma unroll
            for (int mt = 0; mt < 4; mt++) {
                const float* base = &cA[(wy * 64 + mt * 16 + g) * GLD + ks * 8 + tq];
                af[mt][0] = __float_as_uint(base[0]);
                af[mt][1] = __float_as_uint(base[8 * GLD]);
                af[mt][2] = __float_as_uint(base[4]);
                af[mt][3] = __float_as_uint(base[8 * GLD + 4]);
            }
            unsigned bf[8][2];
#pragma unroll
            for (int nt = 0; nt < 8; nt++) {
                const float* base = &cB[(wx * 64 + nt * 8 + g) * GLD + ks * 8 + tq];
                bf[nt][0] = __float_as_uint(base[0]);
                bf[nt][1] = __float_as_uint(base[4]);
            }
#pragma unroll
            for (int mt = 0; mt < 4; mt++)
#pragma unroll
                for (int nt = 0; nt < 8; nt++)
                    mma_tf32(acc[mt][nt][0], acc[mt][nt][1], acc[mt][nt][2], acc[mt][nt][3],
                             af[mt][0], af[mt][1], af[mt][2], af[mt][3], bf[nt][0], bf[nt][1]);
        }
    }
#pragma unroll
    for (int mt = 0; mt < 4; mt++) {
        int r0 = m0 + wy * 64 + mt * 16 + g;
#pragma unroll
        for (int nt = 0; nt < 8; nt++) {
            int col = n0 + wx * 64 + nt * 8 + tq * 2;
            float c0 = acc[mt][nt][0], c1 = acc[mt][nt][1];
            float c2 = acc[mt][nt][2], c3 = acc[mt][nt][3];
            if (ROUND) { c0 = tf32f(c0); c1 = tf32f(c1); c2 = tf32f(c2); c3 = tf32f(c3); }
            *reinterpret_cast<float2*>(C + (size_t)r0 * N + col)       = make_float2(c0, c1);
            *reinterpret_cast<float2*>(C + (size_t)(r0 + 8) * N + col) = make_float2(c2, c3);
        }
    }
}

// ---------------------------------------------------------------------------
__global__ void rmsnorm_qk(float* __restrict__ qkv,
                           const float* __restrict__ qg, const float* __restrict__ kg)
{
    int warp = (blockIdx.x * blockDim.x + threadIdx.x) >> 5;
    int lane = threadIdx.x & 31;
    const int half = B_ * S_ * H_;
    int part = warp / half;
    int rem  = warp % half;
    float* p = qkv + (size_t)(rem / H_) * E_ + part * D_ + (rem % H_) * HD_;
    float4 v = *reinterpret_cast<const float4*>(p + lane * 4);
    float ss = v.x*v.x + v.y*v.y + v.z*v.z + v.w*v.w;
#pragma unroll
    for (int o = 16; o; o >>= 1) ss += __shfl_xor_sync(0xffffffffu, ss, o);
    float sc = rsqrtf(ss * (1.0f / 128.0f) + EPS_);
    const float* gam = part ? kg : qg;
    float4 gv = *reinterpret_cast<const float4*>(gam + lane * 4);
    v.x = tf32f(v.x * sc * gv.x); v.y = tf32f(v.y * sc * gv.y);
    v.z = tf32f(v.z * sc * gv.z); v.w = tf32f(v.w * sc * gv.w);
    *reinterpret_cast<float4*>(p + lane * 4) = v;
}

// ---------------------------------------------------------------------------
// Causal flash attention v4: tf32 MMA + FIXED-MAX softmax (no online rescale).
// 128 threads = 4 warps, BQ=64, BKV=32, 3-stage cp.async ring.
// p = 2^(s*sc2 - M2); O accumulates uncorrected; l = per-thread partial sum,
// reduced once at the end.
// ---------------------------------------------------------------------------
#define AKL 132
#define AVL 136
#define KST (32 * AKL)
#define VST (32 * AVL)

__global__ __launch_bounds__(128, 2) void attn_v4(
    const float* __restrict__ qkv, const float* __restrict__ m2p,
    float* __restrict__ out)
{
    extern __shared__ float sm[];
    float* sK = sm;
    float* sV = sm + 3 * KST;

    const int t    = threadIdx.x;
    const int w    = t >> 5;
    const int lane = t & 31;
    const int g    = lane >> 2;
    const int tq   = lane & 3;

    const int bh   = blockIdx.x >> 5;
    const int qblk = 31 - (blockIdx.x & 31);
    const int b    = bh >> 4;
    const int h    = bh & 15;

    const float* qb = qkv + (size_t)b * S_ * E_ + h * HD_;
    const float* kb = qb + D_;
    const float* vb = qb + 2 * D_;
    const int q0  = qblk * 64;
    const int qg0 = q0 + w * 16 + g;
    const int qg1 = qg0 + 8;
    const float M2 = m2p[0];

    unsigned qf[16][4];
#pragma unroll
    for (int ks = 0; ks < 16; ks++) {
        qf[ks][0] = __float_as_uint(qb[(size_t)qg0 * E_ + ks * 8 + tq]);
        qf[ks][1] = __float_as_uint(qb[(size_t)qg1 * E_ + ks * 8 + tq]);
        qf[ks][2] = __float_as_uint(qb[(size_t)qg0 * E_ + ks * 8 + tq + 4]);
        qf[ks][3] = __float_as_uint(qb[(size_t)qg1 * E_ + ks * 8 + tq + 4]);
    }

    float acc[16][4];
#pragma unroll
    for (int i = 0; i < 16; i++)
#pragma unroll
        for (int r = 0; r < 4; r++) acc[i][r] = 0.f;
    float l0 = 0.f, l1 = 0.f;
    const float sc2 = 0.08838834764831845f * 1.4426950408889634f;

    auto issue = [&](int j, int st) {
        int k0 = j * 32;
#pragma unroll
        for (int u = 0; u < 8; u++) {
            int i = u * 128 + t;
            int r = i >> 5, c4 = i & 31;
            cp_async16(&sK[st * KST + r * AKL + c4 * 4], kb + (size_t)(k0 + r) * E_ + c4 * 4);
            cp_async16(&sV[st * VST + r * AVL + c4 * 4], vb + (size_t)(k0 + r) * E_ + c4 * 4);
        }
        cp_commit();
    };

    const int nblk = 2 * qblk + 2;
    issue(0, 0);
    issue(1, 1);

    const int src0 = (lane & ~3) | (tq >> 1);
    const int src1 = src0 + 2;
    const bool odd = (tq & 1);

    for (int j = 0; j < nblk; j++) {
        if (j + 1 < nblk) cp_wait1(); else cp_wait0();
        __syncthreads();
        if (j + 2 < nblk) issue(j + 2, (j + 2) % 3);

        const float* cK = &sK[(j % 3) * KST];
        const float* cV = &sV[(j % 3) * VST];
        const int k0 = j * 32;

        // ---- S = Q K^T ----
        float sa[4][4];
#pragma unroll
        for (int nt = 0; nt < 4; nt++)
#pragma unroll
            for (int r = 0; r < 4; r++) sa[nt][r] = 0.f;
#pragma unroll
        for (int ks = 0; ks < 16; ks++) {
#pragma unroll
            for (int nt = 0; nt < 4; nt++) {
                const float* bbase = &cK[(nt * 8 + g) * AKL + ks * 8 + tq];
                unsigned b0 = __float_as_uint(bbase[0]);
                unsigned b1 = __float_as_uint(bbase[4]);
                mma_tf32(sa[nt][0], sa[nt][1], sa[nt][2], sa[nt][3],
                         qf[ks][0], qf[ks][1], qf[ks][2], qf[ks][3], b0, b1);
            }
        }

        // ---- fixed-max softmax: p = 2^(s*sc2 - M2), masked -> 0 ----
        if (k0 + 31 > q0 + w * 16) {
#pragma unroll
            for (int nt = 0; nt < 4; nt++) {
                int kva = k0 + nt * 8 + tq * 2;
                float p0 = ex2f(fmaf(sa[nt][0], sc2, -M2));
                float p1 = ex2f(fmaf(sa[nt][1], sc2, -M2));
                float p2 = ex2f(fmaf(sa[nt][2], sc2, -M2));
                float p3 = ex2f(fmaf(sa[nt][3], sc2, -M2));
                p0 = (kva     <= qg0) ? p0 : 0.f;
                p1 = (kva + 1 <= qg0) ? p1 : 0.f;
                p2 = (kva     <= qg1) ? p2 : 0.f;
                p3 = (kva + 1 <= qg1) ? p3 : 0.f;
                l0 += p0 + p1; l1 += p2 + p3;
                sa[nt][0] = tf32f(p0); sa[nt][1] = tf32f(p1);
                sa[nt][2] = tf32f(p2); sa[nt][3] = tf32f(p3);
            }
        } else {
#pragma unroll
            for (int nt = 0; nt < 4; nt++) {
                float p0 = ex2f(fmaf(sa[nt][0], sc2, -M2));
                float p1 = ex2f(fmaf(sa[nt][1], sc2, -M2));
                float p2 = ex2f(fmaf(sa[nt][2], sc2, -M2));
                float p3 = ex2f(fmaf(sa[nt][3], sc2, -M2));
                l0 += p0 + p1; l1 += p2 + p3;
                sa[nt][0] = tf32f(p0); sa[nt][1] = tf32f(p1);
                sa[nt][2] = tf32f(p2); sa[nt][3] = tf32f(p3);
            }
        }

        // ---- PV: A-frags from C-frags via quad shuffles; accumulate (no rescale) ----
#pragma unroll
        for (int ks = 0; ks < 4; ks++) {
            float e0 = __shfl_sync(0xffffffffu, sa[ks][0], src0);
            float e1 = __shfl_sync(0xffffffffu, sa[ks][1], src0);
            float f0 = __shfl_sync(0xffffffffu, sa[ks][0], src1);
            float f1 = __shfl_sync(0xffffffffu, sa[ks][1], src1);
            float e2 = __shfl_sync(0xffffffffu, sa[ks][2], src0);
            float e3 = __shfl_sync(0xffffffffu, sa[ks][3], src0);
            float f2 = __shfl_sync(0xffffffffu, sa[ks][2], src1);
            float f3 = __shfl_sync(0xffffffffu, sa[ks][3], src1);
            unsigned a0 = __float_as_uint(odd ? e1 : e0);
            unsigned a2 = __float_as_uint(odd ? f1 : f0);
            unsigned a1 = __float_as_uint(odd ? e3 : e2);
            unsigned a3 = __float_as_uint(odd ? f3 : f2);
            const float* vr0 = &cV[(ks * 8 + tq) * AVL];
            const float* vr1 = &cV[(ks * 8 + tq + 4) * AVL];
#pragma unroll
            for (int nt = 0; nt < 16; nt++) {
                unsigned b0 = __float_as_uint(vr0[nt * 8 + g]);
                unsigned b1 = __float_as_uint(vr1[nt * 8 + g]);
                mma_tf32(acc[nt][0], acc[nt][1], acc[nt][2], acc[nt][3],
                         a0, a1, a2, a3, b0, b1);
            }
        }
    }

    // final l reduction across the quad (kv columns split over 4 threads)
    l0 += __shfl_xor_sync(0xffffffffu, l0, 1);
    l0 += __shfl_xor_sync(0xffffffffu, l0, 2);
    l1 += __shfl_xor_sync(0xffffffffu, l1, 1);
    l1 += __shfl_xor_sync(0xffffffffu, l1, 2);

    float inv0 = 1.0f / l0, inv1 = 1.0f / l1;
    float* o0 = out + (size_t)(b * S_ + qg0) * D_ + h * HD_;
    float* o1 = out + (size_t)(b * S_ + qg1) * D_ + h * HD_;
#pragma unroll
    for (int nt = 0; nt < 16; nt++) {
        int d = nt * 8 + tq * 2;
        *reinterpret_cast<float2*>(o0 + d) =
            make_float2(tf32f(acc[nt][0] * inv0), tf32f(acc[nt][1] * inv0));
        *reinterpret_cast<float2*>(o1 + d) =
            make_float2(tf32f(acc[nt][2] * inv1), tf32f(acc[nt][3] * inv1));
    }
}

// ---------------------------------------------------------------------------
extern "C" void kernel_launch(void* const* d_in, const int* in_sizes, int n_in,
                              void* d_out, int out_size)
{
    const float* x     = (const float*)d_in[0];
    const float* w_in  = (const float*)d_in[1];
    const float* w_out = (const float*)d_in[2];
    const float* qg    = (const float*)d_in[3];
    const float* kg    = (const float*)d_in[4];
    float* out = (float*)d_out;

    float *qkv, *att, *xr, *wir, *wor, *m2;
    cudaGetSymbolAddress((void**)&qkv, g_qkv);
    cudaGetSymbolAddress((void**)&att, g_att);
    cudaGetSymbolAddress((void**)&xr,  g_xr);
    cudaGetSymbolAddress((void**)&wir, g_wir);
    cudaGetSymbolAddress((void**)&wor, g_wor);
    cudaGetSymbolAddress((void**)&m2,  g_m2);

    round_tf32<<<1184, 256>>>(x,     xr,  BS_ * D_ / 4);
    round_tf32<<<1184, 256>>>(w_in,  wir, E_  * D_ / 4);
    round_tf32<<<1184, 256>>>(w_out, wor, D_  * D_ / 4);
    gmax_kernel<<<1, 32>>>(qg, kg, m2);

    const int gsm = 6 * GST * 4;
    cudaFuncSetAttribute(gemm_tf32_v2<true>,  cudaFuncAttributeMaxDynamicSharedMemorySize, gsm);
    cudaFuncSetAttribute(gemm_tf32_v2<false>, cudaFuncAttributeMaxDynamicSharedMemorySize, gsm);

    gemm_tf32_v2<true><<<dim3(E_ / 128, BS_ / 128), 128, gsm>>>(xr, wir, qkv, BS_, E_, D_);
    rmsnorm_qk<<<32768, 256>>>(qkv, qg, kg);

    const int asm_ = 3 * (KST + VST) * 4;
    cudaFuncSetAttribute(attn_v4, cudaFuncAttributeMaxDynamicSharedMemorySize, asm_);
    attn_v4<<<64 * 32, 128, asm_>>>(qkv, m2, att);

    gemm_tf32_v2<false><<<dim3(D_ / 128, BS_ / 128), 128, gsm>>>(att, wor, out, BS_, D_, D_);
}